// round 11
// baseline (speedup 1.0000x reference)
#include <cuda_runtime.h>
#include <cuda_fp16.h>
#include <cstdint>

// Problem constants: B=8, N=8192, D=256, K=3
#define BB 8
#define NN 8192
#define DD 256
#define KK 3
#define TOKENS (BB * NN)            // 65536

#define CTA_M 128                   // tokens per CTA
#define KC 32                       // contract chunk (2 k16 MMA steps)
#define MMA_CHUNKS 18               // 576 k via MMA (tap0, tap1, tap2 e<64)
#define FF_CHUNKS 6                 // 192 k via FFMA2 (tap2 e 64..255)
#define S_STRIDE 40                 // halves; conflict-free fragment patterns
#define AF_STRIDE 36                // halves; rows r,r+8,r+16,r+24 distinct banks
#define BF_STRIDE 132               // floats; 16B-aligned rows

struct Tap { int fi, ci; float cf, cc; };

// __device__ scratch (no allocation allowed)
__device__ Tap    d_taps[TOKENS * KK];        // 3 MB
__device__ __half d_Wh[DD * KK * DD];         // 384 KB: d_Wh[n][tap*256+e]
__device__ float  d_Wf[192 * DD];             // 192 KB: d_Wf[k][n] = w[n][64+k][2]

__device__ __forceinline__ void mma_f16(float* c, const uint32_t* a,
                                        uint32_t b0, uint32_t b1) {
    asm volatile(
        "mma.sync.aligned.m16n8k16.row.col.f32.f16.f16.f32 "
        "{%0,%1,%2,%3}, {%4,%5,%6,%7}, {%8,%9}, {%0,%1,%2,%3};"
        : "+f"(c[0]), "+f"(c[1]), "+f"(c[2]), "+f"(c[3])
        : "r"(a[0]), "r"(a[1]), "r"(a[2]), "r"(a[3]), "r"(b0), "r"(b1));
}

// ---------------------------------------------------------------------------
// Kernel 1: weight builds. d_Wh[n][tap*256+e] (half) + d_Wf[e-64][n] (f32, tap2).
// ---------------------------------------------------------------------------
__global__ void build_w_kernel(const float* __restrict__ w) {
    int idx = blockIdx.x * blockDim.x + threadIdx.x;   // (n, e)
    if (idx >= DD * DD) return;
    int n = idx >> 8, e = idx & 255;
    float w2 = 0.0f;
#pragma unroll
    for (int tap = 0; tap < KK; ++tap) {
        float v = w[(n * DD + e) * KK + tap];
        d_Wh[n * (KK * DD) + tap * DD + e] = __float2half(v);
        if (tap == 2) w2 = v;
    }
    if (e >= 64) d_Wf[(e - 64) * DD + n] = w2;
}

// ---------------------------------------------------------------------------
// Kernel 2: per-token tap parameters (one warp per token). Proven R6-R8.
// ---------------------------------------------------------------------------
__global__ void compute_taps_kernel(const float* __restrict__ x,
                                    const float* __restrict__ ow,
                                    const float* __restrict__ mw) {
    int gw   = (blockIdx.x * blockDim.x + threadIdx.x) >> 5;
    int lane = threadIdx.x & 31;
    if (gw >= TOKENS) return;

    const float* xr = x + (long long)gw * DD;
    float s0 = 0.f, s1 = 0.f, s2 = 0.f, s3 = 0.f, s4 = 0.f, s5 = 0.f;
#pragma unroll
    for (int i = 0; i < DD / 32; ++i) {
        int e = lane + (i << 5);
        float v = xr[e];
        s0 += v * __ldg(ow + e);
        s1 += v * __ldg(ow + DD + e);
        s2 += v * __ldg(ow + 2 * DD + e);
        s3 += v * __ldg(mw + e);
        s4 += v * __ldg(mw + DD + e);
        s5 += v * __ldg(mw + 2 * DD + e);
    }
#pragma unroll
    for (int off = 16; off > 0; off >>= 1) {
        s0 += __shfl_xor_sync(0xffffffffu, s0, off);
        s1 += __shfl_xor_sync(0xffffffffu, s1, off);
        s2 += __shfl_xor_sync(0xffffffffu, s2, off);
        s3 += __shfl_xor_sync(0xffffffffu, s3, off);
        s4 += __shfl_xor_sync(0xffffffffu, s4, off);
        s5 += __shfl_xor_sync(0xffffffffu, s5, off);
    }
    if (lane == 0) {
        int n = gw & (NN - 1);
        float offs[3] = { s0, s1, s2 };
        float mraw[3] = { s3, s4, s5 };
#pragma unroll
        for (int k = 0; k < KK; ++k) {
            float pos = (float)(n + k - 1) + offs[k];
            float m   = 1.0f / (1.0f + expf(-mraw[k]));
            bool valid = (pos >= 0.0f) && (pos < (float)NN);
            float ff = floorf(pos);
            ff = fminf(fmaxf(ff, 0.0f), (float)(NN - 1));
            int fi = (int)ff;
            int ci = min(fi + 1, NN - 1);
            float wc = pos - ff;
            float coef = valid ? m : 0.0f;
            Tap t;
            t.fi = fi; t.ci = ci;
            t.cf = coef * (1.0f - wc);
            t.cc = coef * wc;
            d_taps[gw * KK + k] = t;
        }
    }
}

// ---------------------------------------------------------------------------
// Kernel 3: hybrid gather-GEMM.
//  - MMA path: 576 k (taps 0,1 + tap2 e<64) via f16 m16n8k16, 18 chunks (R7 core).
//  - FFMA path: 192 k (tap2 e 64..255) via packed fma.rn.f32x2 on the fp32 pipe,
//    overlapped with the MMA dispatch; accumulates into the SAME fp32 fragments.
// CTA: 128 tokens x 128 cols (2 n-halves via grid). 8 warps 4m x 2n.
// ---------------------------------------------------------------------------
__global__ __launch_bounds__(256)
void gemm_hybrid_kernel(const float* __restrict__ x, float* __restrict__ out) {
    __shared__ __half As[CTA_M * S_STRIDE];      // MMA A tile   (10.0 KB)
    __shared__ __half Bs[128 * S_STRIDE];        // MMA B tile   (10.0 KB)
    __shared__ __half Af[CTA_M * AF_STRIDE];     // FFMA A chunk ( 9.0 KB)
    __shared__ float  Bf[KC * BF_STRIDE];        // FFMA B chunk (16.5 KB)

    const int tid  = threadIdx.x;
    const int wid  = tid >> 5;
    const int lane = tid & 31;
    const int wm   = wid & 3;
    const int wn   = wid >> 2;
    const int grp  = lane >> 2;
    const int tg   = lane & 3;

    const int tile = blockIdx.x >> 1;
    const int nh   = blockIdx.x & 1;
    const int tok0 = tile * CTA_M;
    const int b    = tok0 >> 13;
    const float* xb = x + (size_t)b * NN * DD;

    // loader roles
    const int a_tok = tid >> 1;       // 0..127
    const int ah    = tid & 1;
    const int fk    = tid >> 3;       // FFMA B row 0..31
    const int fn8   = tid & 7;        // FFMA B col group

    // per-thread taps for token a_tok
    Tap t0 = d_taps[(tok0 + a_tok) * KK + 0];
    Tap t1 = d_taps[(tok0 + a_tok) * KK + 1];
    Tap t2 = d_taps[(tok0 + a_tok) * KK + 2];

    float acc[2][8][4];
#pragma unroll
    for (int mi = 0; mi < 2; ++mi)
#pragma unroll
        for (int ni = 0; ni < 8; ++ni)
#pragma unroll
            for (int j = 0; j < 4; ++j) acc[mi][ni][j] = 0.0f;

    float4 pa[4];        // MMA A prefetch (16 f32)
    uint4  pb[2];        // MMA B prefetch (16 halves)
    uint2  pfa[4];       // FFMA A prefetch (16 halves, packed)
    float4 pfb[4];       // FFMA B prefetch (16 f32)

    const __half* whb = d_Wh + (size_t)(nh * 128 + a_tok) * (KK * DD) + ah * 16;

    // ---- prologue: MMA chunk 0 into regs; FFMA chunk 0 direct into SMEM
    {
        const float4* pf = (const float4*)(xb + t0.fi * DD + ah * 16);
        const float4* pc = (const float4*)(xb + t0.ci * DD + ah * 16);
#pragma unroll
        for (int j = 0; j < 4; ++j) {
            float4 vf = pf[j], vc = pc[j];
            pa[j].x = fmaf(t0.cf, vf.x, t0.cc * vc.x);
            pa[j].y = fmaf(t0.cf, vf.y, t0.cc * vc.y);
            pa[j].z = fmaf(t0.cf, vf.z, t0.cc * vc.z);
            pa[j].w = fmaf(t0.cf, vf.w, t0.cc * vc.w);
        }
        const uint4* bs = (const uint4*)whb;
        pb[0] = bs[0]; pb[1] = bs[1];

        // FFMA chunk 0: tap2, e0 = 64
        const float4* ff = (const float4*)(xb + t2.fi * DD + 64 + ah * 16);
        const float4* fc = (const float4*)(xb + t2.ci * DD + 64 + ah * 16);
#pragma unroll
        for (int j = 0; j < 4; ++j) {
            float4 vf = ff[j], vc = fc[j];
            __half2 h0 = __floats2half2_rn(fmaf(t2.cf, vf.x, t2.cc * vc.x),
                                           fmaf(t2.cf, vf.y, t2.cc * vc.y));
            __half2 h1 = __floats2half2_rn(fmaf(t2.cf, vf.z, t2.cc * vc.z),
                                           fmaf(t2.cf, vf.w, t2.cc * vc.w));
            uint2 u; u.x = *(uint32_t*)&h0; u.y = *(uint32_t*)&h1;
            *(uint2*)&Af[a_tok * AF_STRIDE + ah * 16 + j * 4] = u;
        }
        const float* wfs = d_Wf + (size_t)fk * DD + nh * 128;
#pragma unroll
        for (int j = 0; j < 4; ++j)
            *(float4*)&Bf[fk * BF_STRIDE + (fn8 + 8 * j) * 4] =
                *(const float4*)(wfs + (fn8 + 8 * j) * 4);
    }

    for (int it = 0; it < MMA_CHUNKS; ++it) {
        __syncthreads();   // previous tiles fully consumed

        // ---- store MMA prefetched tiles
        {
            uint4 ha;
            __half2* hp = (__half2*)&ha;
            hp[0] = __floats2half2_rn(pa[0].x, pa[0].y);
            hp[1] = __floats2half2_rn(pa[0].z, pa[0].w);
            hp[2] = __floats2half2_rn(pa[1].x, pa[1].y);
            hp[3] = __floats2half2_rn(pa[1].z, pa[1].w);
            *(uint4*)&As[a_tok * S_STRIDE + ah * 16] = ha;
            hp[0] = __floats2half2_rn(pa[2].x, pa[2].y);
            hp[1] = __floats2half2_rn(pa[2].z, pa[2].w);
            hp[2] = __floats2half2_rn(pa[3].x, pa[3].y);
            hp[3] = __floats2half2_rn(pa[3].z, pa[3].w);
            *(uint4*)&As[a_tok * S_STRIDE + ah * 16 + 8] = ha;
            *(uint4*)&Bs[a_tok * S_STRIDE + ah * 16] = pb[0];
            *(uint4*)&Bs[a_tok * S_STRIDE + ah * 16 + 8] = pb[1];
        }
        // ---- store FFMA prefetched chunk (every 3rd iteration)
        if (it > 0 && (it % 3) == 0) {
#pragma unroll
            for (int j = 0; j < 4; ++j)
                *(uint2*)&Af[a_tok * AF_STRIDE + ah * 16 + j * 4] = pfa[j];
#pragma unroll
            for (int j = 0; j < 4; ++j)
                *(float4*)&Bf[fk * BF_STRIDE + (fn8 + 8 * j) * 4] = pfb[j];
        }
        __syncthreads();   // tiles visible

        // ---- prefetch next MMA chunk
        if (it + 1 < MMA_CHUNKS) {
            const int cn  = it + 1;
            const int tap = cn >> 3;
            const int e0  = (cn & 7) << 5;
            Tap t = (tap == 0) ? t0 : (tap == 1) ? t1 : t2;
            const float4* pf = (const float4*)(xb + t.fi * DD + e0 + ah * 16);
            const float4* pc = (const float4*)(xb + t.ci * DD + e0 + ah * 16);
#pragma unroll
            for (int j = 0; j < 4; ++j) {
                float4 vf = pf[j], vc = pc[j];
                pa[j].x = fmaf(t.cf, vf.x, t.cc * vc.x);
                pa[j].y = fmaf(t.cf, vf.y, t.cc * vc.y);
                pa[j].z = fmaf(t.cf, vf.z, t.cc * vc.z);
                pa[j].w = fmaf(t.cf, vf.w, t.cc * vc.w);
            }
            const uint4* bs = (const uint4*)(whb + cn * KC);
            pb[0] = bs[0]; pb[1] = bs[1];
        }
        // ---- prefetch next FFMA chunk (it = 2,5,8,11,14 -> fc 1..5)
        if ((it % 3) == 2 && it < MMA_CHUNKS - 1) {
            const int fcn = it / 3 + 1;
            const int e0  = 64 + fcn * KC;
            const float4* ff = (const float4*)(xb + t2.fi * DD + e0 + ah * 16);
            const float4* fc = (const float4*)(xb + t2.ci * DD + e0 + ah * 16);
#pragma unroll
            for (int j = 0; j < 4; ++j) {
                float4 vf = ff[j], vc = fc[j];
                __half2 h0 = __floats2half2_rn(fmaf(t2.cf, vf.x, t2.cc * vc.x),
                                               fmaf(t2.cf, vf.y, t2.cc * vc.y));
                __half2 h1 = __floats2half2_rn(fmaf(t2.cf, vf.z, t2.cc * vc.z),
                                               fmaf(t2.cf, vf.w, t2.cc * vc.w));
                pfa[j].x = *(uint32_t*)&h0; pfa[j].y = *(uint32_t*)&h1;
            }
            const float* wfs = d_Wf + ((size_t)fcn * KC + fk) * DD + nh * 128;
#pragma unroll
            for (int j = 0; j < 4; ++j)
                pfb[j] = *(const float4*)(wfs + (fn8 + 8 * j) * 4);
        }

        // ---- MMA compute: 2 k16 steps (tensor-unit path)
#pragma unroll
        for (int ks = 0; ks < 2; ++ks) {
            const int k0 = ks * 16;
            uint32_t afr[2][4];
#pragma unroll
            for (int mi = 0; mi < 2; ++mi) {
                int row = wm * 32 + mi * 16;
                afr[mi][0] = *(const uint32_t*)&As[(row + grp    ) * S_STRIDE + k0 + 2 * tg    ];
                afr[mi][1] = *(const uint32_t*)&As[(row + grp + 8) * S_STRIDE + k0 + 2 * tg    ];
                afr[mi][2] = *(const uint32_t*)&As[(row + grp    ) * S_STRIDE + k0 + 2 * tg + 8];
                afr[mi][3] = *(const uint32_t*)&As[(row + grp + 8) * S_STRIDE + k0 + 2 * tg + 8];
            }
#pragma unroll
            for (int ni = 0; ni < 8; ++ni) {
                int col = wn * 64 + ni * 8 + grp;
                uint32_t b0 = *(const uint32_t*)&Bs[col * S_STRIDE + k0 + 2 * tg    ];
                uint32_t b1 = *(const uint32_t*)&Bs[col * S_STRIDE + k0 + 2 * tg + 8];
                mma_f16(acc[0][ni], afr[0], b0, b1);
                mma_f16(acc[1][ni], afr[1], b0, b1);
            }
        }

        // ---- FFMA compute (fp32 pipe, overlaps MMA dispatch):
        // chunk fc = it/3, k-slice by it%3 (11,11,10)
        {
            const int s    = it % 3;
            const int k_lo = (s == 0) ? 0 : (s == 1) ? 11 : 22;
            const int k_hi = (s == 2) ? 32 : k_lo + 11;
            const int r0   = wm * 32 + grp;
            const int cb   = wn * 64 + 2 * tg;

            unsigned long long acc2[4][8];
#pragma unroll
            for (int j = 0; j < 4; ++j)
#pragma unroll
                for (int ni = 0; ni < 8; ++ni) acc2[j][ni] = 0ull;

            for (int k = k_lo; k < k_hi; ++k) {
                unsigned long long a2[4];
#pragma unroll
                for (int j = 0; j < 4; ++j) {
                    float a = __half2float(Af[(r0 + j * 8) * AF_STRIDE + k]);
                    asm("mov.b64 %0, {%1, %1};" : "=l"(a2[j]) : "f"(a));
                }
                const float* brow = &Bf[k * BF_STRIDE + cb];
#pragma unroll
                for (int ni = 0; ni < 8; ++ni) {
                    unsigned long long bv = *(const unsigned long long*)(brow + ni * 8);
#pragma unroll
                    for (int j = 0; j < 4; ++j)
                        asm("fma.rn.f32x2 %0, %1, %2, %0;"
                            : "+l"(acc2[j][ni]) : "l"(a2[j]), "l"(bv));
                }
            }
            // drain into the shared fp32 fragment accumulators
#pragma unroll
            for (int j = 0; j < 4; ++j) {
                const int mi = j >> 1, h = j & 1;
#pragma unroll
                for (int ni = 0; ni < 8; ++ni) {
                    uint32_t lo, hi;
                    asm("mov.b64 {%0, %1}, %2;" : "=r"(lo), "=r"(hi) : "l"(acc2[j][ni]));
                    acc[mi][ni][h * 2 + 0] += __uint_as_float(lo);
                    acc[mi][ni][h * 2 + 1] += __uint_as_float(hi);
                }
            }
        }
    }

    // ---- epilogue (R7 mapping; FFMA contributions already merged)
#pragma unroll
    for (int mi = 0; mi < 2; ++mi) {
        size_t row = (size_t)tok0 + wm * 32 + mi * 16 + grp;
        float* op0 = out + row * DD + nh * 128 + wn * 64;
        float* op1 = op0 + 8 * DD;
#pragma unroll
        for (int ni = 0; ni < 8; ++ni) {
            int col = ni * 8 + tg * 2;
            float2 v0 = { acc[mi][ni][0], acc[mi][ni][1] };
            float2 v1 = { acc[mi][ni][2], acc[mi][ni][3] };
            *(float2*)(op0 + col) = v0;
            *(float2*)(op1 + col) = v1;
        }
    }
}

// ---------------------------------------------------------------------------
// Launch (graph-capturable: kernel launches only)
// ---------------------------------------------------------------------------
extern "C" void kernel_launch(void* const* d_in, const int* in_sizes, int n_in,
                              void* d_out, int out_size) {
    const float* x  = (const float*)d_in[0];
    const float* ow = (const float*)d_in[1];
    const float* mw = (const float*)d_in[2];
    const float* w  = (const float*)d_in[3];
    float* out = (float*)d_out;
    (void)in_sizes; (void)n_in; (void)out_size;

    build_w_kernel<<<(DD * DD + 255) / 256, 256>>>(w);
    compute_taps_kernel<<<TOKENS / 8, 256>>>(x, ow, mw);
    gemm_hybrid_kernel<<<(TOKENS / CTA_M) * 2, 256>>>(x, out);
}